// round 4
// baseline (speedup 1.0000x reference)
#include <cuda_runtime.h>
#include <cstdint>

// LatticeCNN on GB300 — closed-form lattice conv decomposition + mma.sync tf32.
//
// join conv  == pointwise with 2-D prefix-summed weights
// meet conv  == pointwise(suffix weights) + x-prefix row strips + y-prefix col
//               strips + 2-D-prefix corner term
//
// Per layer: 1521 GEMM units [64 x Fin] * [Fin x 128], each as one 256-thread
// block running m16n8k8 tf32 mma.sync (portable PTX; works on base sm_103
// target the harness uses — tcgen05 is unavailable there).

#define ALPHA  0.5f
#define SLOPE  0.01f
#define S      32
#define FOUT   128

__device__ __forceinline__ uint32_t to_tf32(float f) {
    uint32_t r; asm("cvt.rna.tf32.f32 %0, %1;" : "=r"(r) : "f"(f)); return r;
}

__device__ __forceinline__ void mma8(float (&d)[4], const uint4& a,
                                     uint32_t b0, uint32_t b1) {
    asm volatile(
        "mma.sync.aligned.m16n8k8.row.col.f32.tf32.tf32.f32 "
        "{%0,%1,%2,%3}, {%4,%5,%6,%7}, {%8,%9}, {%0,%1,%2,%3};"
        : "+f"(d[0]), "+f"(d[1]), "+f"(d[2]), "+f"(d[3])
        : "r"(a.x), "r"(a.y), "r"(a.z), "r"(a.w), "r"(b0), "r"(b1));
}

// ---------------- device scratch (no allocation allowed) ----------------
__device__ float d_Xt0 [1024 * 64 * 64];     // layer0 input, pixel-major [p][m][f]
__device__ float d_Yt  [1024 * 64 * 128];    // layer0 out / layer1 in
__device__ float d_Yt2 [1024 * 64 * 128];    // layer1 out (pixel-major)
__device__ float d_WCT [225 * 128 * FOUT];   // combined pointwise weights [class][g][f]
__device__ float d_MRST[64 * 128 * FOUT];    // row-suffix weights  [a*8+q][g][f]
__device__ float d_MCST[64 * 128 * FOUT];    // col-suffix weights  [p*8+b][g][f]
__device__ float d_MWT [64 * 128 * FOUT];    // raw meet weights    [a*8+b][g][f]
__device__ float d_G   [224 * 64 * FOUT];    // row strip tiles  G[a][y]
__device__ float d_CG  [224 * 64 * FOUT];    // col strip tiles  CG[b][x]
__device__ float d_H   [49  * 64 * FOUT];    // corner tiles     H[a][b]

// ---------------- tiled transpose: dst[C][R] = src[R][C] ----------------
__global__ void transpose_k(float* __restrict__ dst, const float* __restrict__ src,
                            int R, int C)
{
    __shared__ float tile[32][33];
    int c0 = blockIdx.x * 32, r0 = blockIdx.y * 32;
    #pragma unroll
    for (int i = 0; i < 4; i++)
        tile[threadIdx.y + 8 * i][threadIdx.x] =
            src[(size_t)(r0 + threadIdx.y + 8 * i) * C + c0 + threadIdx.x];
    __syncthreads();
    #pragma unroll
    for (int i = 0; i < 4; i++)
        dst[(size_t)(c0 + threadIdx.y + 8 * i) * R + r0 + threadIdx.x] =
            tile[threadIdx.x][threadIdx.y + 8 * i];
}

// ---------------- per-layer weight-table prep (writes [g][f] tables) ------
__global__ void prep_k(const float* __restrict__ mw, const float* __restrict__ jw,
                       float* __restrict__ WCT, float* __restrict__ MRST,
                       float* __restrict__ MCST, float* __restrict__ MWT, int Fin)
{
    int idx = blockIdx.x * blockDim.x + threadIdx.x;
    if (idx >= Fin * FOUT) return;
    int f = idx >> 7, g = idx & 127;
    int ss = Fin * FOUT;
    int src = f * FOUT + g;          // original [a][b][f][g]
    int tb  = g * Fin + f;           // transposed [g][f]

    float m[8][8];
    #pragma unroll
    for (int a = 0; a < 8; a++)
        #pragma unroll
        for (int b = 0; b < 8; b++) {
            m[a][b] = mw[(a * 8 + b) * ss + src];
            MWT[(a * 8 + b) * ss + tb] = m[a][b];
        }

    {   // MCS[p][b] = sum_{a>=p} mw[a][b]
        float col[8];
        #pragma unroll
        for (int b = 0; b < 8; b++) col[b] = 0.f;
        #pragma unroll
        for (int p = 7; p >= 0; p--)
            #pragma unroll
            for (int b = 0; b < 8; b++) {
                col[b] += m[p][b];
                MCST[(p * 8 + b) * ss + tb] = col[b];
            }
    }
    #pragma unroll
    for (int a = 0; a < 8; a++) {    // MRS[a][q] = sum_{b>=q}
        #pragma unroll
        for (int q = 6; q >= 0; q--) m[a][q] += m[a][q + 1];
        #pragma unroll
        for (int q = 0; q < 8; q++) MRST[(a * 8 + q) * ss + tb] = m[a][q];
    }
    #pragma unroll
    for (int b = 0; b < 8; b++)      // -> 2-D suffix MS
        #pragma unroll
        for (int a = 6; a >= 0; a--) m[a][b] += m[a + 1][b];

    float j[8][8];
    #pragma unroll
    for (int a = 0; a < 8; a++)
        #pragma unroll
        for (int b = 0; b < 8; b++)
            j[a][b] = jw[(a * 8 + b) * ss + src];
    #pragma unroll
    for (int a = 0; a < 8; a++)
        #pragma unroll
        for (int b = 1; b < 8; b++) j[a][b] += j[a][b - 1];
    #pragma unroll
    for (int b = 0; b < 8; b++)
        #pragma unroll
        for (int a = 1; a < 8; a++) j[a][b] += j[a - 1][b];

    for (int cx = 0; cx < 15; cx++) {
        int ax = cx < 8 ? 0 : cx - 7;
        int jx = cx < 8 ? cx : 7;
        for (int cy = 0; cy < 15; cy++) {
            int ay = cy < 8 ? 0 : cy - 7;
            int jy = cy < 8 ? cy : 7;
            WCT[(cx * 15 + cy) * ss + tb] =
                (1.0f - ALPHA) * m[ax][ay] + ALPHA * j[jx][jy];
        }
    }
}

// ---------------- GEMM unit: [64 x FIN] * W^T[128 x FIN] -> acc regs -------
// 8 warps: warp (wm,wn) = (wid/4, wid%4) owns rows [wm*32,+32) x cols [wn*32,+32).
// smem: A fragment-packed 16*FIN uint4, B fragment-packed 32*FIN uint4.
template <int FIN>
__device__ __forceinline__ void unit_gemm(const float* __restrict__ X,
                                          const float* __restrict__ W,
                                          uint4* sm, float (&acc)[2][4][4])
{
    constexpr int KT = FIN / 8;
    uint4* Asm = sm;
    uint4* Bsm = sm + 16 * FIN;
    const int tid = threadIdx.x;

    // stage A: slot s -> {X[r][c], X[r+8][c], X[r][c+4], X[r+8][c+4]}
    #pragma unroll
    for (int s = tid; s < 16 * FIN; s += 256) {
        int lane = s & 31, g5 = s >> 5;
        int kt = g5 % KT, mtwm = g5 / KT;
        int r = (mtwm >> 1) * 32 + (mtwm & 1) * 16 + (lane >> 2);
        int c = kt * 8 + (lane & 3);
        const float* p = X + r * FIN + c;
        Asm[s] = make_uint4(to_tf32(__ldg(p)),           to_tf32(__ldg(p + 8 * FIN)),
                            to_tf32(__ldg(p + 4)),       to_tf32(__ldg(p + 8 * FIN + 4)));
    }
    // stage B: slot s -> {W[c0][k], W[c0][k+4], W[c0+8][k], W[c0+8][k+4]}
    #pragma unroll
    for (int s = tid; s < 32 * FIN; s += 256) {
        int lane = s & 31, np = (s >> 5) & 1, g6 = s >> 6;
        int kt = g6 % KT, wn = g6 / KT;
        int c0 = wn * 32 + np * 16 + (lane >> 2);
        int k = kt * 8 + (lane & 3);
        const float* p = W + c0 * FIN + k;
        Bsm[s] = make_uint4(to_tf32(__ldg(p)),           to_tf32(__ldg(p + 4)),
                            to_tf32(__ldg(p + 8 * FIN)), to_tf32(__ldg(p + 8 * FIN + 4)));
    }
    __syncthreads();

    const int lane = tid & 31, wid = tid >> 5;
    const int wm = wid >> 2, wn = wid & 3;
    const uint4* Ap = Asm + (wm * 2) * KT * 32 + lane;
    const uint4* Bp = Bsm + (wn * KT) * 2 * 32 + lane;

    #pragma unroll
    for (int kt = 0; kt < KT; kt++) {
        uint4 a0 = Ap[kt * 32];
        uint4 a1 = Ap[(KT + kt) * 32];
        uint4 b0 = Bp[(kt * 2) * 32];
        uint4 b1 = Bp[(kt * 2 + 1) * 32];
        mma8(acc[0][0], a0, b0.x, b0.y); mma8(acc[0][1], a0, b0.z, b0.w);
        mma8(acc[0][2], a0, b1.x, b1.y); mma8(acc[0][3], a0, b1.z, b1.w);
        mma8(acc[1][0], a1, b0.x, b0.y); mma8(acc[1][1], a1, b0.z, b0.w);
        mma8(acc[1][2], a1, b1.x, b1.y); mma8(acc[1][3], a1, b1.z, b1.w);
    }
}

// ---------------- strips/corner: 497 units, 1 per block ----------------
template <int FIN>
__global__ void __launch_bounds__(256) strips_mc(
    const float* __restrict__ Xt, const float* __restrict__ MRST,
    const float* __restrict__ MCST, const float* __restrict__ MWT,
    float* __restrict__ G, float* __restrict__ CG, float* __restrict__ H)
{
    extern __shared__ uint4 sm[];
    int u = blockIdx.x;
    size_t ss = (size_t)FIN * FOUT;
    const float* X; const float* W; float* dst;
    if (u < 224) {
        int a = u >> 5, Y = u & 31;
        int q = Y > 24 ? Y - 24 : 0;
        X = Xt + (size_t)((a + 24) * S + Y) * 64 * FIN;
        W = MRST + (size_t)(a * 8 + q) * ss;
        dst = G + (size_t)u * 64 * FOUT;
    } else if (u < 448) {
        int t = u - 224;
        int b = t >> 5, Xc = t & 31;
        int p = Xc > 24 ? Xc - 24 : 0;
        X = Xt + (size_t)(Xc * S + b + 24) * 64 * FIN;
        W = MCST + (size_t)(p * 8 + b) * ss;
        dst = CG + (size_t)t * 64 * FOUT;
    } else {
        int t = u - 448;
        int a = t / 7, b = t % 7;
        X = Xt + (size_t)((a + 24) * S + b + 24) * 64 * FIN;
        W = MWT + (size_t)(a * 8 + b) * ss;
        dst = H + (size_t)t * 64 * FOUT;
    }

    float acc[2][4][4] = {};
    unit_gemm<FIN>(X, W, sm, acc);

    int lane = threadIdx.x & 31, wid = threadIdx.x >> 5;
    int wm = wid >> 2, wn = wid & 3;
    int r0 = wm * 32 + (lane >> 2);
    #pragma unroll
    for (int mt = 0; mt < 2; mt++)
        #pragma unroll
        for (int nt = 0; nt < 4; nt++) {
            int g = wn * 32 + nt * 8 + (lane & 3) * 2;
            int r = r0 + mt * 16;
            *(float2*)(dst + r * FOUT + g)       = make_float2(acc[mt][nt][0], acc[mt][nt][1]);
            *(float2*)(dst + (r + 8) * FOUT + g) = make_float2(acc[mt][nt][2], acc[mt][nt][3]);
        }
}

// ---------------- prefix passes ----------------
__global__ void prefix_rows2_k(float* __restrict__ G, float* __restrict__ CG)
{
    int t = blockIdx.x * blockDim.x + threadIdx.x;
    float* buf = (t < 32 * 8192) ? G : CG;
    int tt = t & (32 * 8192 - 1);
    int yy = tt >> 13, mg = tt & 8191;
    float run = 0.f;
    #pragma unroll
    for (int a = 0; a < 7; a++) {
        int idx = (a * 32 + yy) * 8192 + mg;
        run += buf[idx];
        buf[idx] = run;
    }
}

__global__ void prefixH_k(float* __restrict__ H)
{
    int mg = blockIdx.x * blockDim.x + threadIdx.x;
    float colA[7];
    #pragma unroll
    for (int b = 0; b < 7; b++) colA[b] = 0.f;
    #pragma unroll
    for (int a = 0; a < 7; a++) {
        float run = 0.f;
        #pragma unroll
        for (int b = 0; b < 7; b++) {
            int idx = (a * 7 + b) * 8192 + mg;
            run += H[idx];
            colA[b] += run;
            H[idx] = colA[b];
        }
    }
}

// ---------------- combine: 1024 pixels, 1 per block ----------------
template <int FIN>
__global__ void __launch_bounds__(256) combine_mc(
    const float* __restrict__ Xt, const float* __restrict__ WCT,
    const float* __restrict__ Gc, const float* __restrict__ CGc,
    const float* __restrict__ Hc, const float* __restrict__ mb,
    const float* __restrict__ jb, float* __restrict__ Yout)
{
    extern __shared__ uint4 sm[];
    int p = blockIdx.x;
    int X = p >> 5, Y = p & 31;
    int cx = X <= 24 ? (X < 7 ? X : 7) : X - 17;
    int cy = Y <= 24 ? (Y < 7 ? Y : 7) : Y - 17;
    size_t ss = (size_t)FIN * FOUT;

    float acc[2][4][4] = {};
    unit_gemm<FIN>(Xt + (size_t)p * 64 * FIN,
                   WCT + (size_t)(cx * 15 + cy) * ss, sm, acc);

    const float ms = 1.0f - ALPHA;
    const float* Gp = (X >= 25) ? Gc + (size_t)((X - 25) * S + Y) * 64 * FOUT : 0;
    const float* Cp = (Y >= 25) ? CGc + (size_t)((Y - 25) * S + X) * 64 * FOUT : 0;
    const float* Hp = (X >= 25 && Y >= 25)
        ? Hc + (size_t)((X - 25) * 7 + (Y - 25)) * 64 * FOUT : 0;

    int lane = threadIdx.x & 31, wid = threadIdx.x >> 5;
    int wm = wid >> 2, wn = wid & 3;
    int r0 = wm * 32 + (lane >> 2);
    float* O = Yout + (size_t)p * 64 * FOUT;

    #pragma unroll
    for (int nt = 0; nt < 4; nt++) {
        int g = wn * 32 + nt * 8 + (lane & 3) * 2;
        float2 bias = make_float2(ms * mb[g]     + ALPHA * jb[g],
                                  ms * mb[g + 1] + ALPHA * jb[g + 1]);
        #pragma unroll
        for (int mt = 0; mt < 2; mt++) {
            #pragma unroll
            for (int half = 0; half < 2; half++) {
                int r = r0 + mt * 16 + half * 8;
                float v0 = acc[mt][nt][half * 2], v1 = acc[mt][nt][half * 2 + 1];
                if (Gp) {
                    float2 s2 = *(const float2*)(Gp + r * FOUT + g);
                    v0 += ms * s2.x; v1 += ms * s2.y;
                }
                if (Cp) {
                    float2 s2 = *(const float2*)(Cp + r * FOUT + g);
                    v0 += ms * s2.x; v1 += ms * s2.y;
                }
                if (Hp) {
                    float2 s2 = *(const float2*)(Hp + r * FOUT + g);
                    v0 += ms * s2.x; v1 += ms * s2.y;
                }
                v0 += bias.x; v1 += bias.y;
                v0 = fmaxf(v0, SLOPE * v0);
                v1 = fmaxf(v1, SLOPE * v1);
                *(float2*)(O + r * FOUT + g) = make_float2(v0, v1);
            }
        }
    }
}

// ---------------- host launch ----------------
extern "C" void kernel_launch(void* const* d_in, const int* in_sizes, int n_in,
                              void* d_out, int out_size)
{
    const float* x   = (const float*)d_in[0];
    const float* mw0 = (const float*)d_in[5];
    const float* mb0 = (const float*)d_in[6];
    const float* jw0 = (const float*)d_in[7];
    const float* jb0 = (const float*)d_in[8];
    const float* mw1 = (const float*)d_in[9];
    const float* mb1 = (const float*)d_in[10];
    const float* jw1 = (const float*)d_in[11];
    const float* jb1 = (const float*)d_in[12];
    float* out = (float*)d_out;

    float *Xt0, *Yt, *Yt2, *WCT, *MRST, *MCST, *MWT, *G, *CG, *H;
    cudaGetSymbolAddress((void**)&Xt0,  d_Xt0);
    cudaGetSymbolAddress((void**)&Yt,   d_Yt);
    cudaGetSymbolAddress((void**)&Yt2,  d_Yt2);
    cudaGetSymbolAddress((void**)&WCT,  d_WCT);
    cudaGetSymbolAddress((void**)&MRST, d_MRST);
    cudaGetSymbolAddress((void**)&MCST, d_MCST);
    cudaGetSymbolAddress((void**)&MWT,  d_MWT);
    cudaGetSymbolAddress((void**)&G,    d_G);
    cudaGetSymbolAddress((void**)&CG,   d_CG);
    cudaGetSymbolAddress((void**)&H,    d_H);

    const int smem64  = 48 * 64  * 16;   // 49152 B
    const int smem128 = 48 * 128 * 16;   // 98304 B
    cudaFuncSetAttribute(strips_mc<64>,   cudaFuncAttributeMaxDynamicSharedMemorySize, smem64);
    cudaFuncSetAttribute(combine_mc<64>,  cudaFuncAttributeMaxDynamicSharedMemorySize, smem64);
    cudaFuncSetAttribute(strips_mc<128>,  cudaFuncAttributeMaxDynamicSharedMemorySize, smem128);
    cudaFuncSetAttribute(combine_mc<128>, cudaFuncAttributeMaxDynamicSharedMemorySize, smem128);

    dim3 tb(32, 8);
    // x [64*64][1024] -> Xt0 [1024][64*64]
    transpose_k<<<dim3(1024 / 32, 4096 / 32), tb>>>(Xt0, x, 4096, 1024);

    // ---- layer 0: Fin = 64 ----
    prep_k<<<(64 * 128) / 256, 256>>>(mw0, jw0, WCT, MRST, MCST, MWT, 64);
    strips_mc<64><<<497, 256, smem64>>>(Xt0, MRST, MCST, MWT, G, CG, H);
    prefix_rows2_k<<<2048, 256>>>(G, CG);
    prefixH_k<<<32, 256>>>(H);
    combine_mc<64><<<1024, 256, smem64>>>(Xt0, WCT, G, CG, H, mb0, jb0, Yt);

    // ---- layer 1: Fin = 128 ----
    prep_k<<<(128 * 128) / 256, 256>>>(mw1, jw1, WCT, MRST, MCST, MWT, 128);
    strips_mc<128><<<497, 256, smem128>>>(Yt, MRST, MCST, MWT, G, CG, H);
    prefix_rows2_k<<<2048, 256>>>(G, CG);
    prefixH_k<<<32, 256>>>(H);
    combine_mc<128><<<1024, 256, smem128>>>(Yt, WCT, G, CG, H, mb1, jb1, Yt2);

    // Yt2 [1024][8192] -> out [8192][1024]
    transpose_k<<<dim3(8192 / 32, 1024 / 32), tb>>>(out, Yt2, 1024, 8192);
}

// round 5
// speedup vs baseline: 1.1133x; 1.1133x over previous
#include <cuda_runtime.h>
#include <cstdint>

// LatticeCNN on GB300 — closed-form lattice conv decomposition + mma.sync tf32.
//
// join conv  == pointwise with 2-D prefix-summed weights
// meet conv  == pointwise(suffix weights) + x-prefix row strips + y-prefix col
//               strips + 2-D-prefix corner term
//
// Per layer: 1521 GEMM units [64 x Fin] * [Fin x 128], one 256-thread block
// each. Staging: coalesced float4 LDG -> tf32 -> padded raw smem (stride ==
// 4 mod 32 makes every m16n8k8 fragment gather conflict-free LDS.32).

#define ALPHA  0.5f
#define SLOPE  0.01f
#define S      32
#define FOUT   128

__device__ __forceinline__ uint32_t to_tf32(float f) {
    uint32_t r; asm("cvt.rna.tf32.f32 %0, %1;" : "=r"(r) : "f"(f)); return r;
}

__device__ __forceinline__ void mma8(float (&d)[4], const uint4& a,
                                     uint32_t b0, uint32_t b1) {
    asm volatile(
        "mma.sync.aligned.m16n8k8.row.col.f32.tf32.tf32.f32 "
        "{%0,%1,%2,%3}, {%4,%5,%6,%7}, {%8,%9}, {%0,%1,%2,%3};"
        : "+f"(d[0]), "+f"(d[1]), "+f"(d[2]), "+f"(d[3])
        : "r"(a.x), "r"(a.y), "r"(a.z), "r"(a.w), "r"(b0), "r"(b1));
}

// ---------------- device scratch (no allocation allowed) ----------------
__device__ float d_Xt0 [1024 * 64 * 64];     // layer0 input, pixel-major [p][m][f]
__device__ float d_Yt  [1024 * 64 * 128];    // layer0 out / layer1 in
__device__ float d_Yt2 [1024 * 64 * 128];    // layer1 out (pixel-major)
__device__ float d_WCT [225 * 128 * FOUT];   // combined pointwise weights [class][g][f]
__device__ float d_MRST[64 * 128 * FOUT];    // row-suffix weights  [a*8+q][g][f]
__device__ float d_MCST[64 * 128 * FOUT];    // col-suffix weights  [p*8+b][g][f]
__device__ float d_MWT [64 * 128 * FOUT];    // raw meet weights    [a*8+b][g][f]
__device__ float d_G   [224 * 64 * FOUT];    // row strip tiles  G[a][y]
__device__ float d_CG  [224 * 64 * FOUT];    // col strip tiles  CG[b][x]
__device__ float d_H   [49  * 64 * FOUT];    // corner tiles     H[a][b]

// ---------------- tiled transpose: dst[C][R] = src[R][C] ----------------
__global__ void transpose_k(float* __restrict__ dst, const float* __restrict__ src,
                            int R, int C)
{
    __shared__ float tile[32][33];
    int c0 = blockIdx.x * 32, r0 = blockIdx.y * 32;
    #pragma unroll
    for (int i = 0; i < 4; i++)
        tile[threadIdx.y + 8 * i][threadIdx.x] =
            src[(size_t)(r0 + threadIdx.y + 8 * i) * C + c0 + threadIdx.x];
    __syncthreads();
    #pragma unroll
    for (int i = 0; i < 4; i++)
        dst[(size_t)(c0 + threadIdx.y + 8 * i) * R + r0 + threadIdx.x] =
            tile[threadIdx.x][threadIdx.y + 8 * i];
}

// ---------------- per-layer weight-table prep (writes [g][f] tables) ------
__global__ void prep_k(const float* __restrict__ mw, const float* __restrict__ jw,
                       float* __restrict__ WCT, float* __restrict__ MRST,
                       float* __restrict__ MCST, float* __restrict__ MWT, int Fin)
{
    int idx = blockIdx.x * blockDim.x + threadIdx.x;
    if (idx >= Fin * FOUT) return;
    int f = idx >> 7, g = idx & 127;
    int ss = Fin * FOUT;
    int src = f * FOUT + g;          // original [a][b][f][g]
    int tb  = g * Fin + f;           // transposed [g][f]

    float m[8][8];
    #pragma unroll
    for (int a = 0; a < 8; a++)
        #pragma unroll
        for (int b = 0; b < 8; b++) {
            m[a][b] = mw[(a * 8 + b) * ss + src];
            MWT[(a * 8 + b) * ss + tb] = m[a][b];
        }

    {   // MCS[p][b] = sum_{a>=p} mw[a][b]
        float col[8];
        #pragma unroll
        for (int b = 0; b < 8; b++) col[b] = 0.f;
        #pragma unroll
        for (int p = 7; p >= 0; p--)
            #pragma unroll
            for (int b = 0; b < 8; b++) {
                col[b] += m[p][b];
                MCST[(p * 8 + b) * ss + tb] = col[b];
            }
    }
    #pragma unroll
    for (int a = 0; a < 8; a++) {    // MRS[a][q] = sum_{b>=q}
        #pragma unroll
        for (int q = 6; q >= 0; q--) m[a][q] += m[a][q + 1];
        #pragma unroll
        for (int q = 0; q < 8; q++) MRST[(a * 8 + q) * ss + tb] = m[a][q];
    }
    #pragma unroll
    for (int b = 0; b < 8; b++)      // -> 2-D suffix MS
        #pragma unroll
        for (int a = 6; a >= 0; a--) m[a][b] += m[a + 1][b];

    float j[8][8];
    #pragma unroll
    for (int a = 0; a < 8; a++)
        #pragma unroll
        for (int b = 0; b < 8; b++)
            j[a][b] = jw[(a * 8 + b) * ss + src];
    #pragma unroll
    for (int a = 0; a < 8; a++)
        #pragma unroll
        for (int b = 1; b < 8; b++) j[a][b] += j[a][b - 1];
    #pragma unroll
    for (int b = 0; b < 8; b++)
        #pragma unroll
        for (int a = 1; a < 8; a++) j[a][b] += j[a - 1][b];

    for (int cx = 0; cx < 15; cx++) {
        int ax = cx < 8 ? 0 : cx - 7;
        int jx = cx < 8 ? cx : 7;
        for (int cy = 0; cy < 15; cy++) {
            int ay = cy < 8 ? 0 : cy - 7;
            int jy = cy < 8 ? cy : 7;
            WCT[(cx * 15 + cy) * ss + tb] =
                (1.0f - ALPHA) * m[ax][ay] + ALPHA * j[jx][jy];
        }
    }
}

// ---------------- GEMM unit: [64 x FIN] * W^T[128 x FIN] -> acc regs -------
// 8 warps: warp (wm,wn) = (wid/4, wid%4) owns rows [wm*32,+32) x cols [wn*32,+32).
// smem: raw tf32 tiles, row stride LD = FIN+4 (== 4 mod 32 -> every fragment
// gather LDS.32 hits bank == lane, conflict-free).
template <int FIN>
__device__ __forceinline__ void unit_gemm(const float* __restrict__ X,
                                          const float* __restrict__ W,
                                          uint32_t* sm, float (&acc)[2][4][4])
{
    constexpr int LD = FIN + 4;
    constexpr int V = FIN / 4;
    uint32_t* Xs = sm;               // [64][LD]
    uint32_t* Ws = sm + 64 * LD;     // [128][LD]
    const int tid = threadIdx.x;

    #pragma unroll
    for (int v = tid; v < 64 * V; v += 256) {
        int r = v / V, k = (v % V) * 4;
        float4 x = *(const float4*)(X + r * FIN + k);
        uint32_t* d = Xs + r * LD + k;
        d[0] = to_tf32(x.x); d[1] = to_tf32(x.y);
        d[2] = to_tf32(x.z); d[3] = to_tf32(x.w);
    }
    #pragma unroll
    for (int v = tid; v < 128 * V; v += 256) {
        int r = v / V, k = (v % V) * 4;
        float4 x = *(const float4*)(W + r * FIN + k);
        uint32_t* d = Ws + r * LD + k;
        d[0] = to_tf32(x.x); d[1] = to_tf32(x.y);
        d[2] = to_tf32(x.z); d[3] = to_tf32(x.w);
    }
    __syncthreads();

    const int lane = tid & 31, wid = tid >> 5;
    const int wm = wid >> 2, wn = wid & 3;
    // A gather base: row wm*32 + l/4, col l%4
    const uint32_t* Ax = Xs + (wm * 32 + (lane >> 2)) * LD + (lane & 3);
    // B gather base: g row wn*32 + l/4, f col l%4
    const uint32_t* Bx = Ws + (wn * 32 + (lane >> 2)) * LD + (lane & 3);

    #pragma unroll
    for (int kt = 0; kt < FIN / 8; kt++) {
        const int ko = kt * 8;
        uint4 a0, a1;
        a0.x = Ax[ko];               a0.y = Ax[8 * LD + ko];
        a0.z = Ax[ko + 4];           a0.w = Ax[8 * LD + ko + 4];
        a1.x = Ax[16 * LD + ko];     a1.y = Ax[24 * LD + ko];
        a1.z = Ax[16 * LD + ko + 4]; a1.w = Ax[24 * LD + ko + 4];
        uint32_t b[4][2];
        #pragma unroll
        for (int nt = 0; nt < 4; nt++) {
            b[nt][0] = Bx[nt * 8 * LD + ko];
            b[nt][1] = Bx[nt * 8 * LD + ko + 4];
        }
        #pragma unroll
        for (int nt = 0; nt < 4; nt++) {
            mma8(acc[0][nt], a0, b[nt][0], b[nt][1]);
            mma8(acc[1][nt], a1, b[nt][0], b[nt][1]);
        }
    }
}

// ---------------- strips/corner: 497 units, 1 per block ----------------
template <int FIN>
__global__ void __launch_bounds__(256) strips_mc(
    const float* __restrict__ Xt, const float* __restrict__ MRST,
    const float* __restrict__ MCST, const float* __restrict__ MWT,
    float* __restrict__ G, float* __restrict__ CG, float* __restrict__ H)
{
    extern __shared__ uint32_t sm[];
    int u = blockIdx.x;
    size_t ss = (size_t)FIN * FOUT;
    const float* X; const float* W; float* dst;
    if (u < 224) {
        int a = u >> 5, Y = u & 31;
        int q = Y > 24 ? Y - 24 : 0;
        X = Xt + (size_t)((a + 24) * S + Y) * 64 * FIN;
        W = MRST + (size_t)(a * 8 + q) * ss;
        dst = G + (size_t)u * 64 * FOUT;
    } else if (u < 448) {
        int t = u - 224;
        int b = t >> 5, Xc = t & 31;
        int p = Xc > 24 ? Xc - 24 : 0;
        X = Xt + (size_t)(Xc * S + b + 24) * 64 * FIN;
        W = MCST + (size_t)(p * 8 + b) * ss;
        dst = CG + (size_t)t * 64 * FOUT;
    } else {
        int t = u - 448;
        int a = t / 7, b = t % 7;
        X = Xt + (size_t)((a + 24) * S + b + 24) * 64 * FIN;
        W = MWT + (size_t)(a * 8 + b) * ss;
        dst = H + (size_t)t * 64 * FOUT;
    }

    float acc[2][4][4] = {};
    unit_gemm<FIN>(X, W, sm, acc);

    int lane = threadIdx.x & 31, wid = threadIdx.x >> 5;
    int wm = wid >> 2, wn = wid & 3;
    int r0 = wm * 32 + (lane >> 2);
    #pragma unroll
    for (int mt = 0; mt < 2; mt++)
        #pragma unroll
        for (int nt = 0; nt < 4; nt++) {
            int g = wn * 32 + nt * 8 + (lane & 3) * 2;
            int r = r0 + mt * 16;
            *(float2*)(dst + r * FOUT + g)       = make_float2(acc[mt][nt][0], acc[mt][nt][1]);
            *(float2*)(dst + (r + 8) * FOUT + g) = make_float2(acc[mt][nt][2], acc[mt][nt][3]);
        }
}

// ---------------- prefix passes ----------------
__global__ void prefix_rows2_k(float* __restrict__ G, float* __restrict__ CG)
{
    int t = blockIdx.x * blockDim.x + threadIdx.x;
    float* buf = (t < 32 * 8192) ? G : CG;
    int tt = t & (32 * 8192 - 1);
    int yy = tt >> 13, mg = tt & 8191;
    float run = 0.f;
    #pragma unroll
    for (int a = 0; a < 7; a++) {
        int idx = (a * 32 + yy) * 8192 + mg;
        run += buf[idx];
        buf[idx] = run;
    }
}

__global__ void prefixH_k(float* __restrict__ H)
{
    int mg = blockIdx.x * blockDim.x + threadIdx.x;
    float colA[7];
    #pragma unroll
    for (int b = 0; b < 7; b++) colA[b] = 0.f;
    #pragma unroll
    for (int a = 0; a < 7; a++) {
        float run = 0.f;
        #pragma unroll
        for (int b = 0; b < 7; b++) {
            int idx = (a * 7 + b) * 8192 + mg;
            run += H[idx];
            colA[b] += run;
            H[idx] = colA[b];
        }
    }
}

// ---------------- combine: 1024 pixels, 1 per block ----------------
template <int FIN>
__global__ void __launch_bounds__(256) combine_mc(
    const float* __restrict__ Xt, const float* __restrict__ WCT,
    const float* __restrict__ Gc, const float* __restrict__ CGc,
    const float* __restrict__ Hc, const float* __restrict__ mb,
    const float* __restrict__ jb, float* __restrict__ Yout)
{
    extern __shared__ uint32_t sm[];
    int p = blockIdx.x;
    int X = p >> 5, Y = p & 31;
    int cx = X <= 24 ? (X < 7 ? X : 7) : X - 17;
    int cy = Y <= 24 ? (Y < 7 ? Y : 7) : Y - 17;
    size_t ss = (size_t)FIN * FOUT;

    float acc[2][4][4] = {};
    unit_gemm<FIN>(Xt + (size_t)p * 64 * FIN,
                   WCT + (size_t)(cx * 15 + cy) * ss, sm, acc);

    const float ms = 1.0f - ALPHA;
    const float* Gp = (X >= 25) ? Gc + (size_t)((X - 25) * S + Y) * 64 * FOUT : 0;
    const float* Cp = (Y >= 25) ? CGc + (size_t)((Y - 25) * S + X) * 64 * FOUT : 0;
    const float* Hp = (X >= 25 && Y >= 25)
        ? Hc + (size_t)((X - 25) * 7 + (Y - 25)) * 64 * FOUT : 0;

    int lane = threadIdx.x & 31, wid = threadIdx.x >> 5;
    int wm = wid >> 2, wn = wid & 3;
    int r0 = wm * 32 + (lane >> 2);
    float* O = Yout + (size_t)p * 64 * FOUT;

    #pragma unroll
    for (int nt = 0; nt < 4; nt++) {
        int g = wn * 32 + nt * 8 + (lane & 3) * 2;
        float2 bias = make_float2(ms * mb[g]     + ALPHA * jb[g],
                                  ms * mb[g + 1] + ALPHA * jb[g + 1]);
        #pragma unroll
        for (int mt = 0; mt < 2; mt++) {
            #pragma unroll
            for (int half = 0; half < 2; half++) {
                int r = r0 + mt * 16 + half * 8;
                float v0 = acc[mt][nt][half * 2], v1 = acc[mt][nt][half * 2 + 1];
                if (Gp) {
                    float2 s2 = *(const float2*)(Gp + r * FOUT + g);
                    v0 += ms * s2.x; v1 += ms * s2.y;
                }
                if (Cp) {
                    float2 s2 = *(const float2*)(Cp + r * FOUT + g);
                    v0 += ms * s2.x; v1 += ms * s2.y;
                }
                if (Hp) {
                    float2 s2 = *(const float2*)(Hp + r * FOUT + g);
                    v0 += ms * s2.x; v1 += ms * s2.y;
                }
                v0 += bias.x; v1 += bias.y;
                v0 = fmaxf(v0, SLOPE * v0);
                v1 = fmaxf(v1, SLOPE * v1);
                *(float2*)(O + r * FOUT + g) = make_float2(v0, v1);
            }
        }
    }
}

// ---------------- host launch ----------------
extern "C" void kernel_launch(void* const* d_in, const int* in_sizes, int n_in,
                              void* d_out, int out_size)
{
    const float* x   = (const float*)d_in[0];
    const float* mw0 = (const float*)d_in[5];
    const float* mb0 = (const float*)d_in[6];
    const float* jw0 = (const float*)d_in[7];
    const float* jb0 = (const float*)d_in[8];
    const float* mw1 = (const float*)d_in[9];
    const float* mb1 = (const float*)d_in[10];
    const float* jw1 = (const float*)d_in[11];
    const float* jb1 = (const float*)d_in[12];
    float* out = (float*)d_out;

    float *Xt0, *Yt, *Yt2, *WCT, *MRST, *MCST, *MWT, *G, *CG, *H;
    cudaGetSymbolAddress((void**)&Xt0,  d_Xt0);
    cudaGetSymbolAddress((void**)&Yt,   d_Yt);
    cudaGetSymbolAddress((void**)&Yt2,  d_Yt2);
    cudaGetSymbolAddress((void**)&WCT,  d_WCT);
    cudaGetSymbolAddress((void**)&MRST, d_MRST);
    cudaGetSymbolAddress((void**)&MCST, d_MCST);
    cudaGetSymbolAddress((void**)&MWT,  d_MWT);
    cudaGetSymbolAddress((void**)&G,    d_G);
    cudaGetSymbolAddress((void**)&CG,   d_CG);
    cudaGetSymbolAddress((void**)&H,    d_H);

    const int smem64  = 192 * (64 + 4)  * 4;   //  52224 B
    const int smem128 = 192 * (128 + 4) * 4;   // 101376 B
    cudaFuncSetAttribute(strips_mc<64>,   cudaFuncAttributeMaxDynamicSharedMemorySize, smem64);
    cudaFuncSetAttribute(combine_mc<64>,  cudaFuncAttributeMaxDynamicSharedMemorySize, smem64);
    cudaFuncSetAttribute(strips_mc<128>,  cudaFuncAttributeMaxDynamicSharedMemorySize, smem128);
    cudaFuncSetAttribute(combine_mc<128>, cudaFuncAttributeMaxDynamicSharedMemorySize, smem128);

    dim3 tb(32, 8);
    // x [64*64][1024] -> Xt0 [1024][64*64]
    transpose_k<<<dim3(1024 / 32, 4096 / 32), tb>>>(Xt0, x, 4096, 1024);

    // ---- layer 0: Fin = 64 ----
    prep_k<<<(64 * 128) / 256, 256>>>(mw0, jw0, WCT, MRST, MCST, MWT, 64);
    strips_mc<64><<<497, 256, smem64>>>(Xt0, MRST, MCST, MWT, G, CG, H);
    prefix_rows2_k<<<2048, 256>>>(G, CG);
    prefixH_k<<<32, 256>>>(H);
    combine_mc<64><<<1024, 256, smem64>>>(Xt0, WCT, G, CG, H, mb0, jb0, Yt);

    // ---- layer 1: Fin = 128 ----
    prep_k<<<(128 * 128) / 256, 256>>>(mw1, jw1, WCT, MRST, MCST, MWT, 128);
    strips_mc<128><<<497, 256, smem128>>>(Yt, MRST, MCST, MWT, G, CG, H);
    prefix_rows2_k<<<2048, 256>>>(G, CG);
    prefixH_k<<<32, 256>>>(H);
    combine_mc<128><<<1024, 256, smem128>>>(Yt, WCT, G, CG, H, mb1, jb1, Yt2);

    // Yt2 [1024][8192] -> out [8192][1024]
    transpose_k<<<dim3(8192 / 32, 1024 / 32), tb>>>(out, Yt2, 1024, 8192);
}

// round 7
// speedup vs baseline: 1.2349x; 1.1092x over previous
#include <cuda_runtime.h>
#include <cuda_fp16.h>
#include <cstdint>

// LatticeCNN on GB300 — closed-form lattice conv decomposition + mma.sync fp16.
//
// join conv  == pointwise with 2-D prefix-summed weights
// meet conv  == pointwise(suffix weights) + x-prefix row strips + y-prefix col
//               strips + 2-D-prefix corner term
//
// Per layer: 1521 GEMM units [64 x Fin] * [Fin x 128], one 256-thread block
// each, m16n8k16 f16 mma.sync (fp32 accum). fp16 mantissa == tf32 mantissa
// (10 bits) so accuracy matches the tf32 path, at 2x FLOP per HMMA.

#define ALPHA  0.5f
#define SLOPE  0.01f
#define S      32
#define FOUT   128

__device__ __forceinline__ uint32_t pack_f16x2(float lo, float hi) {
    uint32_t r;
    asm("cvt.rn.f16x2.f32 %0, %1, %2;" : "=r"(r) : "f"(hi), "f"(lo));
    return r;
}

__device__ __forceinline__ void mma16(float (&d)[4], const uint4& a,
                                      uint32_t b0, uint32_t b1) {
    asm volatile(
        "mma.sync.aligned.m16n8k16.row.col.f32.f16.f16.f32 "
        "{%0,%1,%2,%3}, {%4,%5,%6,%7}, {%8,%9}, {%0,%1,%2,%3};"
        : "+f"(d[0]), "+f"(d[1]), "+f"(d[2]), "+f"(d[3])
        : "r"(a.x), "r"(a.y), "r"(a.z), "r"(a.w), "r"(b0), "r"(b1));
}

// ---------------- device scratch (no allocation allowed) ----------------
__device__ float d_Xt0 [1024 * 64 * 64];     // layer0 input, pixel-major [p][m][f]
__device__ float d_Yt  [1024 * 64 * 128];    // layer0 out / layer1 in
__device__ float d_Yt2 [1024 * 64 * 128];    // layer1 out (pixel-major)
__device__ float d_WCT [225 * 128 * FOUT];   // combined pointwise weights [class][g][f]
__device__ float d_MRST[64 * 128 * FOUT];    // row-suffix weights  [a*8+q][g][f]
__device__ float d_MCST[64 * 128 * FOUT];    // col-suffix weights  [p*8+b][g][f]
__device__ float d_MWT [64 * 128 * FOUT];    // raw meet weights    [a*8+b][g][f]
__device__ float d_G   [224 * 64 * FOUT];    // row strip tiles  G[a][y]
__device__ float d_CG  [224 * 64 * FOUT];    // col strip tiles  CG[b][x]
__device__ float d_H   [49  * 64 * FOUT];    // corner tiles     H[a][b]

// ---------------- tiled transpose: dst[C][R] = src[R][C] ----------------
__global__ void transpose_k(float* __restrict__ dst, const float* __restrict__ src,
                            int R, int C)
{
    __shared__ float tile[32][33];
    int c0 = blockIdx.x * 32, r0 = blockIdx.y * 32;
    #pragma unroll
    for (int i = 0; i < 4; i++)
        tile[threadIdx.y + 8 * i][threadIdx.x] =
            src[(size_t)(r0 + threadIdx.y + 8 * i) * C + c0 + threadIdx.x];
    __syncthreads();
    #pragma unroll
    for (int i = 0; i < 4; i++)
        dst[(size_t)(c0 + threadIdx.y + 8 * i) * R + r0 + threadIdx.x] =
            tile[threadIdx.x][threadIdx.y + 8 * i];
}

// ---------------- per-layer weight-table prep (writes [g][f] tables) ------
__global__ void prep_k(const float* __restrict__ mw, const float* __restrict__ jw,
                       float* __restrict__ WCT, float* __restrict__ MRST,
                       float* __restrict__ MCST, float* __restrict__ MWT, int Fin)
{
    int idx = blockIdx.x * blockDim.x + threadIdx.x;
    if (idx >= Fin * FOUT) return;
    int f = idx >> 7, g = idx & 127;
    int ss = Fin * FOUT;
    int src = f * FOUT + g;          // original [a][b][f][g]
    int tb  = g * Fin + f;           // transposed [g][f]

    float m[8][8];
    #pragma unroll
    for (int a = 0; a < 8; a++)
        #pragma unroll
        for (int b = 0; b < 8; b++) {
            m[a][b] = mw[(a * 8 + b) * ss + src];
            MWT[(a * 8 + b) * ss + tb] = m[a][b];
        }

    {   // MCS[p][b] = sum_{a>=p} mw[a][b]
        float col[8];
        #pragma unroll
        for (int b = 0; b < 8; b++) col[b] = 0.f;
        #pragma unroll
        for (int p = 7; p >= 0; p--)
            #pragma unroll
            for (int b = 0; b < 8; b++) {
                col[b] += m[p][b];
                MCST[(p * 8 + b) * ss + tb] = col[b];
            }
    }
    #pragma unroll
    for (int a = 0; a < 8; a++) {    // MRS[a][q] = sum_{b>=q}
        #pragma unroll
        for (int q = 6; q >= 0; q--) m[a][q] += m[a][q + 1];
        #pragma unroll
        for (int q = 0; q < 8; q++) MRST[(a * 8 + q) * ss + tb] = m[a][q];
    }
    #pragma unroll
    for (int b = 0; b < 8; b++)      // -> 2-D suffix MS
        #pragma unroll
        for (int a = 6; a >= 0; a--) m[a][b] += m[a + 1][b];

    float j[8][8];
    #pragma unroll
    for (int a = 0; a < 8; a++)
        #pragma unroll
        for (int b = 0; b < 8; b++)
            j[a][b] = jw[(a * 8 + b) * ss + src];
    #pragma unroll
    for (int a = 0; a < 8; a++)
        #pragma unroll
        for (int b = 1; b < 8; b++) j[a][b] += j[a][b - 1];
    #pragma unroll
    for (int b = 0; b < 8; b++)
        #pragma unroll
        for (int a = 1; a < 8; a++) j[a][b] += j[a - 1][b];

    for (int cx = 0; cx < 15; cx++) {
        int ax = cx < 8 ? 0 : cx - 7;
        int jx = cx < 8 ? cx : 7;
        for (int cy = 0; cy < 15; cy++) {
            int ay = cy < 8 ? 0 : cy - 7;
            int jy = cy < 8 ? cy : 7;
            WCT[(cx * 15 + cy) * ss + tb] =
                (1.0f - ALPHA) * m[ax][ay] + ALPHA * j[jx][jy];
        }
    }
}

// ---------------- GEMM unit: [64 x FIN] * W^T[128 x FIN] -> acc regs -------
// 8 warps: warp (wm,wn) = (wid/4, wid%4) owns rows [wm*32,+32) x cols [wn*32,+32).
// smem: raw fp16 tiles, halfword stride LDh = FIN+8 (LDh/2 == 4 mod 32 ->
// every f16x2 fragment gather is a conflict-free LDS.32).
template <int FIN>
__device__ __forceinline__ void unit_gemm(const float* __restrict__ X,
                                          const float* __restrict__ W,
                                          __half* sm, float (&acc)[2][4][4])
{
    constexpr int LDh = FIN + 8;
    constexpr int V = FIN / 4;
    __half* Xs = sm;                 // [64][LDh]
    __half* Ws = sm + 64 * LDh;      // [128][LDh]
    const int tid = threadIdx.x;

    #pragma unroll
    for (int v = tid; v < 64 * V; v += 256) {
        int r = v / V, k = (v % V) * 4;
        float4 x = *(const float4*)(X + r * FIN + k);
        uint2 h;
        h.x = pack_f16x2(x.x, x.y);
        h.y = pack_f16x2(x.z, x.w);
        *(uint2*)(Xs + r * LDh + k) = h;
    }
    #pragma unroll
    for (int v = tid; v < 128 * V; v += 256) {
        int r = v / V, k = (v % V) * 4;
        float4 x = *(const float4*)(W + r * FIN + k);
        uint2 h;
        h.x = pack_f16x2(x.x, x.y);
        h.y = pack_f16x2(x.z, x.w);
        *(uint2*)(Ws + r * LDh + k) = h;
    }
    __syncthreads();

    const int lane = tid & 31, wid = tid >> 5;
    const int wm = wid >> 2, wn = wid & 3;
    const __half* Ax = Xs + (wm * 32 + (lane >> 2)) * LDh + (lane & 3) * 2;
    const __half* Bx = Ws + (wn * 32 + (lane >> 2)) * LDh + (lane & 3) * 2;

    #pragma unroll
    for (int kt = 0; kt < FIN / 16; kt++) {
        const int k0 = kt * 16;
        uint4 a0, a1;
        a0.x = *(const uint32_t*)(Ax + k0);
        a0.y = *(const uint32_t*)(Ax + 8 * LDh + k0);
        a0.z = *(const uint32_t*)(Ax + k0 + 8);
        a0.w = *(const uint32_t*)(Ax + 8 * LDh + k0 + 8);
        a1.x = *(const uint32_t*)(Ax + 16 * LDh + k0);
        a1.y = *(const uint32_t*)(Ax + 24 * LDh + k0);
        a1.z = *(const uint32_t*)(Ax + 16 * LDh + k0 + 8);
        a1.w = *(const uint32_t*)(Ax + 24 * LDh + k0 + 8);
        uint32_t b[4][2];
        #pragma unroll
        for (int nt = 0; nt < 4; nt++) {
            b[nt][0] = *(const uint32_t*)(Bx + nt * 8 * LDh + k0);
            b[nt][1] = *(const uint32_t*)(Bx + nt * 8 * LDh + k0 + 8);
        }
        #pragma unroll
        for (int nt = 0; nt < 4; nt++) {
            mma16(acc[0][nt], a0, b[nt][0], b[nt][1]);
            mma16(acc[1][nt], a1, b[nt][0], b[nt][1]);
        }
    }
}

// ---------------- strips/corner: 497 units, 1 per block ----------------
template <int FIN>
__global__ void __launch_bounds__(256) strips_mc(
    const float* __restrict__ Xt, const float* __restrict__ MRST,
    const float* __restrict__ MCST, const float* __restrict__ MWT,
    float* __restrict__ G, float* __restrict__ CG, float* __restrict__ H)
{
    extern __shared__ __half smh[];
    int u = blockIdx.x;
    size_t ss = (size_t)FIN * FOUT;
    const float* X; const float* W; float* dst;
    if (u < 224) {
        int a = u >> 5, Y = u & 31;
        int q = Y > 24 ? Y - 24 : 0;
        X = Xt + (size_t)((a + 24) * S + Y) * 64 * FIN;
        W = MRST + (size_t)(a * 8 + q) * ss;
        dst = G + (size_t)u * 64 * FOUT;
    } else if (u < 448) {
        int t = u - 224;
        int b = t >> 5, Xc = t & 31;
        int p = Xc > 24 ? Xc - 24 : 0;
        X = Xt + (size_t)(Xc * S + b + 24) * 64 * FIN;
        W = MCST + (size_t)(p * 8 + b) * ss;
        dst = CG + (size_t)t * 64 * FOUT;
    } else {
        int t = u - 448;
        int a = t / 7, b = t % 7;
        X = Xt + (size_t)((a + 24) * S + b + 24) * 64 * FIN;
        W = MWT + (size_t)(a * 8 + b) * ss;
        dst = H + (size_t)t * 64 * FOUT;
    }

    float acc[2][4][4] = {};
    unit_gemm<FIN>(X, W, smh, acc);

    int lane = threadIdx.x & 31, wid = threadIdx.x >> 5;
    int wm = wid >> 2, wn = wid & 3;
    int r0 = wm * 32 + (lane >> 2);
    #pragma unroll
    for (int mt = 0; mt < 2; mt++)
        #pragma unroll
        for (int nt = 0; nt < 4; nt++) {
            int g = wn * 32 + nt * 8 + (lane & 3) * 2;
            int r = r0 + mt * 16;
            *(float2*)(dst + r * FOUT + g)       = make_float2(acc[mt][nt][0], acc[mt][nt][1]);
            *(float2*)(dst + (r + 8) * FOUT + g) = make_float2(acc[mt][nt][2], acc[mt][nt][3]);
        }
}

// ---------------- merged prefix pass: rows(G) + rows(CG) + 2-D(H) ----------
__global__ void prefix_all_k(float* __restrict__ G, float* __restrict__ CG,
                             float* __restrict__ H)
{
    int bid = blockIdx.x;
    if (bid < 2048) {
        int t = bid * 256 + threadIdx.x;
        float* buf = (t < 32 * 8192) ? G : CG;
        int tt = t & (32 * 8192 - 1);
        int yy = tt >> 13, mg = tt & 8191;
        float run = 0.f;
        #pragma unroll
        for (int a = 0; a < 7; a++) {
            int idx = (a * 32 + yy) * 8192 + mg;
            run += buf[idx];
            buf[idx] = run;
        }
    } else {
        int mg = (bid - 2048) * 256 + threadIdx.x;
        float colA[7];
        #pragma unroll
        for (int b = 0; b < 7; b++) colA[b] = 0.f;
        #pragma unroll
        for (int a = 0; a < 7; a++) {
            float run = 0.f;
            #pragma unroll
            for (int b = 0; b < 7; b++) {
                int idx = (a * 7 + b) * 8192 + mg;
                run += H[idx];
                colA[b] += run;
                H[idx] = colA[b];
            }
        }
    }
}

// ---------------- combine: 1024 pixels, 1 per block ----------------
template <int FIN>
__global__ void __launch_bounds__(256) combine_mc(
    const float* __restrict__ Xt, const float* __restrict__ WCT,
    const float* __restrict__ Gc, const float* __restrict__ CGc,
    const float* __restrict__ Hc, const float* __restrict__ mb,
    const float* __restrict__ jb, float* __restrict__ Yout)
{
    extern __shared__ __half smh[];
    int p = blockIdx.x;
    int X = p >> 5, Y = p & 31;
    int cx = X <= 24 ? (X < 7 ? X : 7) : X - 17;
    int cy = Y <= 24 ? (Y < 7 ? Y : 7) : Y - 17;
    size_t ss = (size_t)FIN * FOUT;

    float acc[2][4][4] = {};
    unit_gemm<FIN>(Xt + (size_t)p * 64 * FIN,
                   WCT + (size_t)(cx * 15 + cy) * ss, smh, acc);

    const float ms = 1.0f - ALPHA;
    const float* Gp = (X >= 25) ? Gc + (size_t)((X - 25) * S + Y) * 64 * FOUT : 0;
    const float* Cp = (Y >= 25) ? CGc + (size_t)((Y - 25) * S + X) * 64 * FOUT : 0;
    const float* Hp = (X >= 25 && Y >= 25)
        ? Hc + (size_t)((X - 25) * 7 + (Y - 25)) * 64 * FOUT : 0;

    int lane = threadIdx.x & 31, wid = threadIdx.x >> 5;
    int wm = wid >> 2, wn = wid & 3;
    int r0 = wm * 32 + (lane >> 2);
    float* O = Yout + (size_t)p * 64 * FOUT;

    #pragma unroll
    for (int nt = 0; nt < 4; nt++) {
        int g = wn * 32 + nt * 8 + (lane & 3) * 2;
        float2 bias = make_float2(ms * mb[g]     + ALPHA * jb[g],
                                  ms * mb[g + 1] + ALPHA * jb[g + 1]);
        #pragma unroll
        for (int mt = 0; mt < 2; mt++) {
            #pragma unroll
            for (int half = 0; half < 2; half++) {
                int r = r0 + mt * 16 + half * 8;
                float v0 = acc[mt][nt][half * 2], v1 = acc[mt][nt][half * 2 + 1];
                if (Gp) {
                    float2 s2 = *(const float2*)(Gp + r * FOUT + g);
                    v0 += ms * s2.x; v1 += ms * s2.y;
                }
                if (Cp) {
                    float2 s2 = *(const float2*)(Cp + r * FOUT + g);
                    v0 += ms * s2.x; v1 += ms * s2.y;
                }
                if (Hp) {
                    float2 s2 = *(const float2*)(Hp + r * FOUT + g);
                    v0 += ms * s2.x; v1 += ms * s2.y;
                }
                v0 += bias.x; v1 += bias.y;
                v0 = fmaxf(v0, SLOPE * v0);
                v1 = fmaxf(v1, SLOPE * v1);
                *(float2*)(O + r * FOUT + g) = make_float2(v0, v1);
            }
        }
    }
}

// ---------------- host launch ----------------
extern "C" void kernel_launch(void* const* d_in, const int* in_sizes, int n_in,
                              void* d_out, int out_size)
{
    const float* x   = (const float*)d_in[0];
    const float* mw0 = (const float*)d_in[5];
    const float* mb0 = (const float*)d_in[6];
    const float* jw0 = (const float*)d_in[7];
    const float* jb0 = (const float*)d_in[8];
    const float* mw1 = (const float*)d_in[9];
    const float* mb1 = (const float*)d_in[10];
    const float* jw1 = (const float*)d_in[11];
    const float* jb1 = (const float*)d_in[12];
    float* out = (float*)d_out;

    float *Xt0, *Yt, *Yt2, *WCT, *MRST, *MCST, *MWT, *G, *CG, *H;
    cudaGetSymbolAddress((void**)&Xt0,  d_Xt0);
    cudaGetSymbolAddress((void**)&Yt,   d_Yt);
    cudaGetSymbolAddress((void**)&Yt2,  d_Yt2);
    cudaGetSymbolAddress((void**)&WCT,  d_WCT);
    cudaGetSymbolAddress((void**)&MRST, d_MRST);
    cudaGetSymbolAddress((void**)&MCST, d_MCST);
    cudaGetSymbolAddress((void**)&MWT,  d_MWT);
    cudaGetSymbolAddress((void**)&G,    d_G);
    cudaGetSymbolAddress((void**)&CG,   d_CG);
    cudaGetSymbolAddress((void**)&H,    d_H);

    const int smem64  = 192 * (64 + 8)  * 2;   // 27648 B
    const int smem128 = 192 * (128 + 8) * 2;   // 52224 B
    cudaFuncSetAttribute(strips_mc<64>,   cudaFuncAttributeMaxDynamicSharedMemorySize, smem64);
    cudaFuncSetAttribute(combine_mc<64>,  cudaFuncAttributeMaxDynamicSharedMemorySize, smem64);
    cudaFuncSetAttribute(strips_mc<128>,  cudaFuncAttributeMaxDynamicSharedMemorySize, smem128);
    cudaFuncSetAttribute(combine_mc<128>, cudaFuncAttributeMaxDynamicSharedMemorySize, smem128);

    dim3 tb(32, 8);
    // x [64*64][1024] -> Xt0 [1024][64*64]
    transpose_k<<<dim3(1024 / 32, 4096 / 32), tb>>>(Xt0, x, 4096, 1024);

    // ---- layer 0: Fin = 64 ----
    prep_k<<<(64 * 128) / 256, 256>>>(mw0, jw0, WCT, MRST, MCST, MWT, 64);
    strips_mc<64><<<497, 256, smem64>>>(Xt0, MRST, MCST, MWT, G, CG, H);
    prefix_all_k<<<2080, 256>>>(G, CG, H);
    combine_mc<64><<<1024, 256, smem64>>>(Xt0, WCT, G, CG, H, mb0, jb0, Yt);

    // ---- layer 1: Fin = 128 ----
    prep_k<<<(128 * 128) / 256, 256>>>(mw1, jw1, WCT, MRST, MCST, MWT, 128);
    strips_mc<128><<<497, 256, smem128>>>(Yt, MRST, MCST, MWT, G, CG, H);
    prefix_all_k<<<2080, 256>>>(G, CG, H);
    combine_mc<128><<<1024, 256, smem128>>>(Yt, WCT, G, CG, H, mb1, jb1, Yt2);

    // Yt2 [1024][8192] -> out [8192][1024]
    transpose_k<<<dim3(8192 / 32, 1024 / 32), tb>>>(out, Yt2, 1024, 8192);
}